// round 1
// baseline (speedup 1.0000x reference)
#include <cuda_runtime.h>
#include <math.h>

// Problem constants
#define NB 128      // batch
#define SS 64       // initial sequence length
#define DD 512      // model dim
#define CHD 2048    // hidden dim of GRC fc1 / per-group width of fc2 output
#define SPLITK 8

// ---------------- device scratch (no allocations allowed) ----------------
__device__ float d_cs[NB * SS * DD];       // chart states, slot-addressed
__device__ float d_C0[NB * SS * DD];       // init GEMM output
__device__ float d_part[SPLITK * NB * CHD];// split-K partial sums (shared fc1/fc2)
__device__ float d_h[NB * CHD];            // fc1 activations
__device__ float d_xcat[NB * 1024];        // [l, r] concat for selected pairs
__device__ float d_logits[NB * 63];
__device__ int   d_idx[NB * SS];           // active slot list per row
__device__ int   d_slotL[NB];
__device__ int   d_slotR[NB];
__device__ int   d_flag[NB];

__device__ __forceinline__ float gelu_f(float x) {
    float x3 = x * x * x;
    return 0.5f * x * (1.0f + tanhf(0.7978845608028654f * (x + 0.044715f * x3)));
}
__device__ __forceinline__ float sigm_f(float x) {
    return 1.0f / (1.0f + expf(-x));
}

// ---------------- generic fp32 SGEMM: C_part[z] = A[:, kz] @ B[kz, :] ----------------
// A: MxK row-major, B: KxN row-major. Block tile 128x128, 8x8 per thread,
// deterministic split-K via blockIdx.z writing disjoint partial buffers.
__global__ __launch_bounds__(256) void sgemm_k(
    const float* __restrict__ A, const float* __restrict__ B, float* __restrict__ Cp,
    int M, int N, int K, int kc)
{
    __shared__ float As[16][128];
    __shared__ float Bs[16][128];
    const int tid = threadIdx.x;
    const int tx = tid & 15;
    const int ty = tid >> 4;
    const int m0 = blockIdx.y * 128;
    const int n0 = blockIdx.x * 128;
    const int k0 = blockIdx.z * kc;
    const int k1 = k0 + kc;

    float acc[8][8];
#pragma unroll
    for (int i = 0; i < 8; i++)
#pragma unroll
        for (int j = 0; j < 8; j++) acc[i][j] = 0.0f;

    const int arow = tid >> 2;          // 0..63
    const int ac4  = (tid & 3) << 2;    // 0,4,8,12
    const int brow = tid >> 5;          // 0..7
    const int bc4  = (tid & 31) << 2;   // 0..124

    for (int kt = k0; kt < k1; kt += 16) {
        float4 a0 = *(const float4*)(A + (size_t)(m0 + arow) * K + kt + ac4);
        float4 a1 = *(const float4*)(A + (size_t)(m0 + arow + 64) * K + kt + ac4);
        float4 b0 = *(const float4*)(B + (size_t)(kt + brow) * N + n0 + bc4);
        float4 b1 = *(const float4*)(B + (size_t)(kt + brow + 8) * N + n0 + bc4);
        As[ac4 + 0][arow] = a0.x; As[ac4 + 1][arow] = a0.y;
        As[ac4 + 2][arow] = a0.z; As[ac4 + 3][arow] = a0.w;
        As[ac4 + 0][arow + 64] = a1.x; As[ac4 + 1][arow + 64] = a1.y;
        As[ac4 + 2][arow + 64] = a1.z; As[ac4 + 3][arow + 64] = a1.w;
        *(float4*)&Bs[brow][bc4]     = b0;
        *(float4*)&Bs[brow + 8][bc4] = b1;
        __syncthreads();
#pragma unroll
        for (int kk = 0; kk < 16; kk++) {
            float av[8], bv[8];
            *(float4*)(av)     = *(const float4*)&As[kk][ty * 8];
            *(float4*)(av + 4) = *(const float4*)&As[kk][ty * 8 + 4];
            *(float4*)(bv)     = *(const float4*)&Bs[kk][tx * 8];
            *(float4*)(bv + 4) = *(const float4*)&Bs[kk][tx * 8 + 4];
#pragma unroll
            for (int i = 0; i < 8; i++)
#pragma unroll
                for (int j = 0; j < 8; j++)
                    acc[i][j] = fmaf(av[i], bv[j], acc[i][j]);
        }
        __syncthreads();
    }

    float* Co = Cp + (size_t)blockIdx.z * M * N;
#pragma unroll
    for (int i = 0; i < 8; i++) {
        float4 v0 = make_float4(acc[i][0], acc[i][1], acc[i][2], acc[i][3]);
        float4 v1 = make_float4(acc[i][4], acc[i][5], acc[i][6], acc[i][7]);
        *(float4*)(Co + (size_t)(m0 + ty * 8 + i) * N + n0 + tx * 8)     = v0;
        *(float4*)(Co + (size_t)(m0 + ty * 8 + i) * N + n0 + tx * 8 + 4) = v1;
    }
}

// ---------------- init LayerNorm: cs = LN(C0 + b_init) * g + beta; also idx init ----------------
__global__ void init_ln_k(const float* __restrict__ b, const float* __restrict__ g,
                          const float* __restrict__ beta)
{
    int row = blockIdx.x;           // 0..8191 == n*64+s
    int tid = threadIdx.x;          // 128
    __shared__ float sv[512];
    __shared__ float red[128];
    const float* src = d_C0 + (size_t)row * 512;
    for (int d = tid; d < 512; d += 128) sv[d] = src[d] + b[d];
    __syncthreads();
    float p = sv[tid] + sv[tid + 128] + sv[tid + 256] + sv[tid + 384];
    red[tid] = p; __syncthreads();
    for (int off = 64; off > 0; off >>= 1) {
        if (tid < off) red[tid] += red[tid + off];
        __syncthreads();
    }
    float mean = red[0] * (1.0f / 512.0f);
    __syncthreads();
    float q = 0.0f;
    for (int d = tid; d < 512; d += 128) { float x = sv[d] - mean; q += x * x; }
    red[tid] = q; __syncthreads();
    for (int off = 64; off > 0; off >>= 1) {
        if (tid < off) red[tid] += red[tid + off];
        __syncthreads();
    }
    float inv = 1.0f / sqrtf(red[0] * (1.0f / 512.0f) + 1e-5f);
    float* dst = d_cs + (size_t)row * 512;
    for (int d = tid; d < 512; d += 128) dst[d] = (sv[d] - mean) * inv * g[d] + beta[d];
    if (tid == 0) d_idx[row] = row & 63;
}

// ---------------- scorer: one warp per (row, pair) ----------------
__global__ __launch_bounds__(256) void scorer_k(
    const float* __restrict__ Wd1, const float* __restrict__ bd1,
    const float* __restrict__ Wd2, const float* __restrict__ bd2,
    const float* __restrict__ mask, int it, int P)
{
    __shared__ float Wd1s[128 * 64];
    __shared__ float Wd2s[64];
    __shared__ float fs[8][128];
    int tid = threadIdx.x;
    for (int t = tid; t < 128 * 64; t += 256) Wd1s[t] = Wd1[t];
    if (tid < 64) Wd2s[tid] = Wd2[tid];
    __syncthreads();
    int w = tid >> 5, lane = tid & 31;
    int p = blockIdx.x * 8 + w;
    if (p >= NB * P) return;
    int n = p / P, j = p - n * P;
    int a  = d_idx[n * 64 + j];
    int bs = d_idx[n * 64 + j + 1];
    const float* lrow = d_cs + (size_t)(n * 64 + a) * 512;
    const float* rrow = d_cs + (size_t)(n * 64 + bs) * 512;
    for (int t = lane; t < 128; t += 32) fs[w][t] = (t < 64) ? lrow[t] : rrow[t - 64];
    __syncwarp();
    float acc0 = 0.0f, acc1 = 0.0f;
#pragma unroll 16
    for (int k = 0; k < 128; k++) {
        float f = fs[w][k];
        acc0 = fmaf(f, Wd1s[k * 64 + lane], acc0);
        acc1 = fmaf(f, Wd1s[k * 64 + lane + 32], acc1);
    }
    float h0 = gelu_f(acc0 + bd1[lane]);
    float h1 = gelu_f(acc1 + bd1[lane + 32]);
    float part = h0 * Wd2s[lane] + h1 * Wd2s[lane + 32];
#pragma unroll
    for (int off = 16; off > 0; off >>= 1)
        part += __shfl_xor_sync(0xffffffffu, part, off);
    if (lane == 0) {
        float lg = part + bd2[0];
        float mv = mask[n * 64 + it + 1 + j];
        d_logits[n * 63 + j] = (mv > 0.0f) ? lg : -1e9f;
    }
}

// ---------------- argmax + index compaction + gather xcat ----------------
__global__ void argmax_k(const float* __restrict__ mask, int it, int Scur, int force0)
{
    int n = blockIdx.x;
    __shared__ int sh[2];
    if (threadIdx.x == 0) {
        int P = Scur - 1;
        int k = 0;
        if (!force0) {
            float best = -3.4e38f;
            for (int j = 0; j < P; j++) {
                float v = d_logits[n * 63 + j];
                if (v > best) { best = v; k = j; }   // first max, matches jnp.argmax
            }
        }
        float done = mask[n * 64 + it + 1];
        int sL, sR, fl;
        if (done > 0.0f) {
            sL = d_idx[n * 64 + k]; sR = d_idx[n * 64 + k + 1]; fl = 1;
            for (int j = k + 1; j < Scur - 1; j++) d_idx[n * 64 + j] = d_idx[n * 64 + j + 1];
        } else {
            sL = d_idx[n * 64]; sR = d_idx[n * 64 + 1]; fl = 0; // dummy compute, no write
        }
        d_slotL[n] = sL; d_slotR[n] = sR; d_flag[n] = fl;
        sh[0] = sL; sh[1] = sR;
    }
    __syncthreads();
    int sL = sh[0], sR = sh[1];
    const float* lrow = d_cs + (size_t)(n * 64 + sL) * 512;
    const float* rrow = d_cs + (size_t)(n * 64 + sR) * 512;
    float* x = d_xcat + (size_t)n * 1024;
    for (int t = threadIdx.x; t < 512; t += 128) {
        x[t] = lrow[t];
        x[512 + t] = rrow[t];
    }
}

// ---------------- fc1 split-K reduce + bias + gelu ----------------
__global__ void fc1red_k(const float* __restrict__ b1)
{
    int id = blockIdx.x * 256 + threadIdx.x;   // < 128*2048
    float s = 0.0f;
#pragma unroll
    for (int z = 0; z < SPLITK; z++) s += d_part[(size_t)z * (NB * CHD) + id];
    d_h[id] = gelu_f(s + b1[id & 2047]);
}

// ---------------- fc2 reduce + gates + LayerNorm + write back into cs ----------------
__global__ void gateln_k(const float* __restrict__ b2, const float* __restrict__ g,
                         const float* __restrict__ beta)
{
    int n = blockIdx.x;
    if (d_flag[n] == 0) return;
    int tid = threadIdx.x;   // 256
    __shared__ float sv[512];
    __shared__ float red[256];
    const float* base = d_part + (size_t)n * 2048;
    for (int d = tid; d < 512; d += 256) {
        float c0 = 0.0f, c1 = 0.0f, c2 = 0.0f, c3 = 0.0f;
#pragma unroll
        for (int z = 0; z < SPLITK; z++) {
            const float* pp = base + (size_t)z * (NB * CHD);
            c0 += pp[d]; c1 += pp[512 + d]; c2 += pp[1024 + d]; c3 += pp[1536 + d];
        }
        c0 += b2[d]; c1 += b2[512 + d]; c2 += b2[1024 + d]; c3 += b2[1536 + d];
        float l = d_xcat[(size_t)n * 1024 + d];
        float r = d_xcat[(size_t)n * 1024 + 512 + d];
        sv[d] = sigm_f(c0) * l + sigm_f(c1) * r + sigm_f(c2) * c3;
    }
    __syncthreads();
    float p = sv[tid] + sv[tid + 256];
    red[tid] = p; __syncthreads();
    for (int off = 128; off > 0; off >>= 1) {
        if (tid < off) red[tid] += red[tid + off];
        __syncthreads();
    }
    float mean = red[0] * (1.0f / 512.0f);
    __syncthreads();
    float d0 = sv[tid] - mean, d1 = sv[tid + 256] - mean;
    red[tid] = d0 * d0 + d1 * d1; __syncthreads();
    for (int off = 128; off > 0; off >>= 1) {
        if (tid < off) red[tid] += red[tid + off];
        __syncthreads();
    }
    float inv = 1.0f / sqrtf(red[0] * (1.0f / 512.0f) + 1e-5f);
    float* dst = d_cs + (size_t)(n * 64 + d_slotL[n]) * 512;
    for (int d = tid; d < 512; d += 256)
        dst[d] = (sv[d] - mean) * inv * g[d] + beta[d];
}

// ---------------- final gather: out[n] = cs[n, idx[n][0]] ----------------
__global__ void gather_k(float* __restrict__ out)
{
    int n = blockIdx.x;
    int s0 = d_idx[n * 64];
    const float* src = d_cs + (size_t)(n * 64 + s0) * 512;
    for (int d = threadIdx.x; d < 512; d += 256)
        out[(size_t)n * 512 + d] = src[d];
}

// ---------------- host launcher (graph-capturable: kernel launches only) ----------------
extern "C" void kernel_launch(void* const* d_in, const int* in_sizes, int n_in,
                              void* d_out, int out_size)
{
    const float* input     = (const float*)d_in[0];
    const float* mask      = (const float*)d_in[1];
    const float* W_init    = (const float*)d_in[2];
    const float* b_init    = (const float*)d_in[3];
    const float* g_init    = (const float*)d_in[4];
    const float* beta_init = (const float*)d_in[5];
    const float* W_d1      = (const float*)d_in[6];
    const float* b_d1      = (const float*)d_in[7];
    const float* W_d2      = (const float*)d_in[8];
    const float* b_d2      = (const float*)d_in[9];
    const float* W_c1      = (const float*)d_in[10];
    const float* b_c1      = (const float*)d_in[11];
    const float* W_c2      = (const float*)d_in[12];
    const float* b_c2      = (const float*)d_in[13];
    const float* g_c       = (const float*)d_in[14];
    const float* beta_c    = (const float*)d_in[15];

    float *p_C0, *p_part, *p_h, *p_xcat;
    cudaGetSymbolAddress((void**)&p_C0,   d_C0);
    cudaGetSymbolAddress((void**)&p_part, d_part);
    cudaGetSymbolAddress((void**)&p_h,    d_h);
    cudaGetSymbolAddress((void**)&p_xcat, d_xcat);

    // init: cs = LN(input @ W_init + b_init)
    sgemm_k<<<dim3(4, 64, 1), 256>>>(input, W_init, p_C0, 8192, 512, 512, 512);
    init_ln_k<<<8192, 128>>>(b_init, g_init, beta_init);

    for (int i = 0; i < 63; i++) {
        int Scur = 64 - i;
        int P = Scur - 1;
        if (i < 62) {
            int pairs = NB * P;
            scorer_k<<<(pairs + 7) / 8, 256>>>(W_d1, b_d1, W_d2, b_d2, mask, i, P);
        }
        argmax_k<<<NB, 128>>>(mask, i, Scur, (i == 62) ? 1 : 0);
        // fc1: xcat(128x1024) @ W_c1(1024x2048), split-K=8 (chunks of 128)
        sgemm_k<<<dim3(16, 1, SPLITK), 256>>>(p_xcat, W_c1, p_part, 128, 2048, 1024, 128);
        fc1red_k<<<(NB * CHD) / 256, 256>>>(b_c1);
        // fc2: h(128x2048) @ W_c2(2048x2048), split-K=8 (chunks of 256)
        sgemm_k<<<dim3(16, 1, SPLITK), 256>>>(p_h, W_c2, p_part, 128, 2048, 2048, 256);
        gateln_k<<<NB, 256>>>(b_c2, g_c, beta_c);
    }
    gather_k<<<NB, 256>>>((float*)d_out);
}

// round 2
// speedup vs baseline: 1.0790x; 1.0790x over previous
#include <cuda_runtime.h>
#include <math.h>

// Problem constants
#define NB 128      // batch
#define SS 64       // initial sequence length
#define DD 512      // model dim
#define CHD 2048    // hidden dim of GRC fc1 / per-group width of fc2 output
#define SPLITK 16

// ---------------- device scratch (no allocations allowed) ----------------
__device__ float d_cs[NB * SS * DD];        // chart states, slot-addressed
__device__ float d_C0[NB * SS * DD];        // init GEMM output
__device__ float d_part[SPLITK * NB * CHD]; // split-K partial sums (shared fc1/fc2)
__device__ float d_h[NB * CHD];             // fc1 activations
__device__ float d_xcat[NB * 1024];         // [l, r] concat for selected pairs
__device__ int   d_idx[NB * SS];            // active slot list per row
__device__ int   d_slotL[NB];
__device__ int   d_flag[NB];

__device__ __forceinline__ float gelu_f(float x) {
    float x3 = x * x * x;
    return 0.5f * x * (1.0f + tanhf(0.7978845608028654f * (x + 0.044715f * x3)));
}
__device__ __forceinline__ float sigm_f(float x) {
    return 1.0f / (1.0f + expf(-x));
}

// ---------------- fp32 SGEMM, double-buffered, 2 CTAs/SM ----------------
// A: MxK row-major, B: KxN row-major. Block tile 128x128, 8x8 per thread,
// deterministic split-K via blockIdx.z writing disjoint partial buffers.
__global__ __launch_bounds__(256, 2) void sgemm_k(
    const float* __restrict__ A, const float* __restrict__ B, float* __restrict__ Cp,
    int M, int N, int K, int kc)
{
    __shared__ float As[2][16][128];
    __shared__ float Bs[2][16][128];
    const int tid = threadIdx.x;
    const int tx = tid & 15;
    const int ty = tid >> 4;
    const int m0 = blockIdx.y * 128;
    const int n0 = blockIdx.x * 128;
    const int k0 = blockIdx.z * kc;
    const int nk = kc >> 4;

    float acc[8][8];
#pragma unroll
    for (int i = 0; i < 8; i++)
#pragma unroll
        for (int j = 0; j < 8; j++) acc[i][j] = 0.0f;

    const int arow = tid >> 2;          // 0..63
    const int ac4  = (tid & 3) << 2;    // 0,4,8,12
    const int brow = tid >> 5;          // 0..7
    const int bc4  = (tid & 31) << 2;   // 0..124

    const float* Ap = A + (size_t)(m0 + arow) * K + k0 + ac4;
    const float* Bp = B + (size_t)(k0 + brow) * N + n0 + bc4;

    // prologue: load tile 0
    float4 a0 = *(const float4*)(Ap);
    float4 a1 = *(const float4*)(Ap + (size_t)64 * K);
    float4 b0 = *(const float4*)(Bp);
    float4 b1 = *(const float4*)(Bp + (size_t)8 * N);
    As[0][ac4 + 0][arow] = a0.x; As[0][ac4 + 1][arow] = a0.y;
    As[0][ac4 + 2][arow] = a0.z; As[0][ac4 + 3][arow] = a0.w;
    As[0][ac4 + 0][arow + 64] = a1.x; As[0][ac4 + 1][arow + 64] = a1.y;
    As[0][ac4 + 2][arow + 64] = a1.z; As[0][ac4 + 3][arow + 64] = a1.w;
    *(float4*)&Bs[0][brow][bc4]     = b0;
    *(float4*)&Bs[0][brow + 8][bc4] = b1;
    __syncthreads();

    int buf = 0;
    for (int t = 0; t < nk; t++) {
        if (t + 1 < nk) {   // prefetch next tile into registers (overlaps compute)
            const float* Apn = Ap + (t + 1) * 16;
            const float* Bpn = Bp + (size_t)(t + 1) * 16 * N;
            a0 = *(const float4*)(Apn);
            a1 = *(const float4*)(Apn + (size_t)64 * K);
            b0 = *(const float4*)(Bpn);
            b1 = *(const float4*)(Bpn + (size_t)8 * N);
        }
#pragma unroll
        for (int kk = 0; kk < 16; kk++) {
            float av[8], bv[8];
            *(float4*)(av)     = *(const float4*)&As[buf][kk][ty * 8];
            *(float4*)(av + 4) = *(const float4*)&As[buf][kk][ty * 8 + 4];
            *(float4*)(bv)     = *(const float4*)&Bs[buf][kk][tx * 8];
            *(float4*)(bv + 4) = *(const float4*)&Bs[buf][kk][tx * 8 + 4];
#pragma unroll
            for (int i = 0; i < 8; i++)
#pragma unroll
                for (int j = 0; j < 8; j++)
                    acc[i][j] = fmaf(av[i], bv[j], acc[i][j]);
        }
        if (t + 1 < nk) {
            int nb = buf ^ 1;
            As[nb][ac4 + 0][arow] = a0.x; As[nb][ac4 + 1][arow] = a0.y;
            As[nb][ac4 + 2][arow] = a0.z; As[nb][ac4 + 3][arow] = a0.w;
            As[nb][ac4 + 0][arow + 64] = a1.x; As[nb][ac4 + 1][arow + 64] = a1.y;
            As[nb][ac4 + 2][arow + 64] = a1.z; As[nb][ac4 + 3][arow + 64] = a1.w;
            *(float4*)&Bs[nb][brow][bc4]     = b0;
            *(float4*)&Bs[nb][brow + 8][bc4] = b1;
            __syncthreads();
            buf = nb;
        }
    }

    float* Co = Cp + (size_t)blockIdx.z * M * N;
#pragma unroll
    for (int i = 0; i < 8; i++) {
        float4 v0 = make_float4(acc[i][0], acc[i][1], acc[i][2], acc[i][3]);
        float4 v1 = make_float4(acc[i][4], acc[i][5], acc[i][6], acc[i][7]);
        *(float4*)(Co + (size_t)(m0 + ty * 8 + i) * N + n0 + tx * 8)     = v0;
        *(float4*)(Co + (size_t)(m0 + ty * 8 + i) * N + n0 + tx * 8 + 4) = v1;
    }
}

// ---------------- init LayerNorm: cs = LN(C0 + b_init) * g + beta; also idx init ----------------
__global__ void init_ln_k(const float* __restrict__ b, const float* __restrict__ g,
                          const float* __restrict__ beta)
{
    int row = blockIdx.x;           // 0..8191 == n*64+s
    int tid = threadIdx.x;          // 128
    __shared__ float sv[512];
    __shared__ float red[128];
    const float* src = d_C0 + (size_t)row * 512;
    for (int d = tid; d < 512; d += 128) sv[d] = src[d] + b[d];
    __syncthreads();
    float p = sv[tid] + sv[tid + 128] + sv[tid + 256] + sv[tid + 384];
    red[tid] = p; __syncthreads();
    for (int off = 64; off > 0; off >>= 1) {
        if (tid < off) red[tid] += red[tid + off];
        __syncthreads();
    }
    float mean = red[0] * (1.0f / 512.0f);
    __syncthreads();
    float q = 0.0f;
    for (int d = tid; d < 512; d += 128) { float x = sv[d] - mean; q += x * x; }
    red[tid] = q; __syncthreads();
    for (int off = 64; off > 0; off >>= 1) {
        if (tid < off) red[tid] += red[tid + off];
        __syncthreads();
    }
    float inv = 1.0f / sqrtf(red[0] * (1.0f / 512.0f) + 1e-5f);
    float* dst = d_cs + (size_t)row * 512;
    for (int d = tid; d < 512; d += 128) dst[d] = (sv[d] - mean) * inv * g[d] + beta[d];
    if (tid == 0) d_idx[row] = row & 63;
}

// ---------------- fused scorer + argmax + compaction + xcat gather ----------------
// One block of 256 threads per batch row. 8 warps score pairs; parallel
// first-max argmax via monotone 64-bit keys; parallel list compaction.
__global__ __launch_bounds__(256) void select_k(
    const float* __restrict__ Wd1, const float* __restrict__ bd1,
    const float* __restrict__ Wd2, const float* __restrict__ bd2,
    const float* __restrict__ mask, int it, int P, int force0)
{
    int n = blockIdx.x;
    int tid = threadIdx.x, w = tid >> 5, lane = tid & 31;
    __shared__ float Wd1s[128 * 64];
    __shared__ float Wd2s[64];
    __shared__ float bd1s[64];
    __shared__ float fs[8][128];
    __shared__ float lg[64];
    __shared__ unsigned long long wmax[8];
    __shared__ int shk[4];   // k, sL, sR, flag

    // preload successor index BEFORE any compaction writes
    int mynext = (tid < 63) ? d_idx[n * 64 + tid + 1] : 0;

    if (!force0) {
        for (int t = tid; t < 128 * 64; t += 256) Wd1s[t] = Wd1[t];
        if (tid < 64) { Wd2s[tid] = Wd2[tid]; bd1s[tid] = bd1[tid]; }
        __syncthreads();
        for (int j = w; j < P; j += 8) {
            int a  = d_idx[n * 64 + j];
            int bs = d_idx[n * 64 + j + 1];
            const float* lrow = d_cs + (size_t)(n * 64 + a) * 512;
            const float* rrow = d_cs + (size_t)(n * 64 + bs) * 512;
            for (int t = lane; t < 128; t += 32)
                fs[w][t] = (t < 64) ? lrow[t] : rrow[t - 64];
            __syncwarp();
            float acc0 = 0.0f, acc1 = 0.0f;
#pragma unroll 16
            for (int k = 0; k < 128; k++) {
                float f = fs[w][k];
                acc0 = fmaf(f, Wd1s[k * 64 + lane], acc0);
                acc1 = fmaf(f, Wd1s[k * 64 + lane + 32], acc1);
            }
            float h0 = gelu_f(acc0 + bd1s[lane]);
            float h1 = gelu_f(acc1 + bd1s[lane + 32]);
            float part = h0 * Wd2s[lane] + h1 * Wd2s[lane + 32];
#pragma unroll
            for (int off = 16; off > 0; off >>= 1)
                part += __shfl_xor_sync(0xffffffffu, part, off);
            if (lane == 0) {
                float mv = mask[n * 64 + it + 1 + j];
                lg[j] = (mv > 0.0f) ? (part + bd2[0]) : -1e9f;
            }
            __syncwarp();  // protect fs[w] before next pair
        }
        __syncthreads();
    }

    // parallel argmax with first-index tie-break: key = (ordered(v) << 32) | (63 - j)
    unsigned long long key = 0ull;
    if (!force0 && tid < P) {
        unsigned u = __float_as_uint(lg[tid]);
        u = (u & 0x80000000u) ? ~u : (u | 0x80000000u);
        key = ((unsigned long long)u << 32) | (unsigned)(63 - tid);
    }
#pragma unroll
    for (int off = 16; off > 0; off >>= 1) {
        unsigned long long o = __shfl_xor_sync(0xffffffffu, key, off);
        if (o > key) key = o;
    }
    if (lane == 0) wmax[w] = key;
    __syncthreads();

    if (tid == 0) {
        unsigned long long best = wmax[0];
#pragma unroll
        for (int i = 1; i < 8; i++) if (wmax[i] > best) best = wmax[i];
        int k = force0 ? 0 : (63 - (int)(best & 0xFFFFFFFFu));
        float done = mask[n * 64 + it + 1];
        int sL = d_idx[n * 64 + k];
        int sR = d_idx[n * 64 + k + 1];
        int fl = (done > 0.0f) ? 1 : 0;
        if (!fl) { sL = d_idx[n * 64]; sR = d_idx[n * 64 + 1]; }
        shk[0] = k; shk[1] = sL; shk[2] = sR; shk[3] = fl;
        d_slotL[n] = sL; d_flag[n] = fl;
    }
    __syncthreads();

    // parallel compaction: idx[j] = idx[j+1] for j in [k+1, P-1]
    if (shk[3] && tid >= shk[0] + 1 && tid <= P - 1)
        d_idx[n * 64 + tid] = mynext;

    // gather xcat = [cs[sL], cs[sR]]
    int sL = shk[1], sR = shk[2];
    const float* lrow = d_cs + (size_t)(n * 64 + sL) * 512;
    const float* rrow = d_cs + (size_t)(n * 64 + sR) * 512;
    float* x = d_xcat + (size_t)n * 1024;
    for (int t = tid; t < 512; t += 256) {
        x[t] = lrow[t];
        x[512 + t] = rrow[t];
    }
}

// ---------------- fc1 split-K reduce + bias + gelu ----------------
__global__ void fc1red_k(const float* __restrict__ b1)
{
    int id = blockIdx.x * 256 + threadIdx.x;   // < 128*2048
    float s = 0.0f;
#pragma unroll
    for (int z = 0; z < SPLITK; z++) s += d_part[(size_t)z * (NB * CHD) + id];
    d_h[id] = gelu_f(s + b1[id & 2047]);
}

// ---------------- fc2 reduce + gates + LayerNorm + write back into cs ----------------
__global__ void gateln_k(const float* __restrict__ b2, const float* __restrict__ g,
                         const float* __restrict__ beta, const float* __restrict__ unused)
{
    int n = blockIdx.x;
    if (d_flag[n] == 0) return;
    int tid = threadIdx.x;   // 256
    __shared__ float sv[512];
    __shared__ float red[256];
    const float* base = d_part + (size_t)n * 2048;
    for (int d = tid; d < 512; d += 256) {
        float c0 = 0.0f, c1 = 0.0f, c2 = 0.0f, c3 = 0.0f;
#pragma unroll
        for (int z = 0; z < SPLITK; z++) {
            const float* pp = base + (size_t)z * (NB * CHD);
            c0 += pp[d]; c1 += pp[512 + d]; c2 += pp[1024 + d]; c3 += pp[1536 + d];
        }
        c0 += b2[d]; c1 += b2[512 + d]; c2 += b2[1024 + d]; c3 += b2[1536 + d];
        float l = d_xcat[(size_t)n * 1024 + d];
        float r = d_xcat[(size_t)n * 1024 + 512 + d];
        sv[d] = sigm_f(c0) * l + sigm_f(c1) * r + sigm_f(c2) * c3;
    }
    __syncthreads();
    float p = sv[tid] + sv[tid + 256];
    red[tid] = p; __syncthreads();
    for (int off = 128; off > 0; off >>= 1) {
        if (tid < off) red[tid] += red[tid + off];
        __syncthreads();
    }
    float mean = red[0] * (1.0f / 512.0f);
    __syncthreads();
    float d0 = sv[tid] - mean, d1 = sv[tid + 256] - mean;
    red[tid] = d0 * d0 + d1 * d1; __syncthreads();
    for (int off = 128; off > 0; off >>= 1) {
        if (tid < off) red[tid] += red[tid + off];
        __syncthreads();
    }
    float inv = 1.0f / sqrtf(red[0] * (1.0f / 512.0f) + 1e-5f);
    float* dst = d_cs + (size_t)(n * 64 + d_slotL[n]) * 512;
    for (int d = tid; d < 512; d += 256)
        dst[d] = (sv[d] - mean) * inv * g[d] + beta[d];
}

// ---------------- final gather: out[n] = cs[n, idx[n][0]] ----------------
__global__ void gather_k(float* __restrict__ out)
{
    int n = blockIdx.x;
    int s0 = d_idx[n * 64];
    const float* src = d_cs + (size_t)(n * 64 + s0) * 512;
    for (int d = threadIdx.x; d < 512; d += 256)
        out[(size_t)n * 512 + d] = src[d];
}

// ---------------- host launcher (graph-capturable: kernel launches only) ----------------
extern "C" void kernel_launch(void* const* d_in, const int* in_sizes, int n_in,
                              void* d_out, int out_size)
{
    const float* input     = (const float*)d_in[0];
    const float* mask      = (const float*)d_in[1];
    const float* W_init    = (const float*)d_in[2];
    const float* b_init    = (const float*)d_in[3];
    const float* g_init    = (const float*)d_in[4];
    const float* beta_init = (const float*)d_in[5];
    const float* W_d1      = (const float*)d_in[6];
    const float* b_d1      = (const float*)d_in[7];
    const float* W_d2      = (const float*)d_in[8];
    const float* b_d2      = (const float*)d_in[9];
    const float* W_c1      = (const float*)d_in[10];
    const float* b_c1      = (const float*)d_in[11];
    const float* W_c2      = (const float*)d_in[12];
    const float* b_c2      = (const float*)d_in[13];
    const float* g_c       = (const float*)d_in[14];
    const float* beta_c    = (const float*)d_in[15];

    float *p_C0, *p_part, *p_h, *p_xcat;
    cudaGetSymbolAddress((void**)&p_C0,   d_C0);
    cudaGetSymbolAddress((void**)&p_part, d_part);
    cudaGetSymbolAddress((void**)&p_h,    d_h);
    cudaGetSymbolAddress((void**)&p_xcat, d_xcat);

    // init: cs = LN(input @ W_init + b_init)
    sgemm_k<<<dim3(4, 64, 1), 256>>>(input, W_init, p_C0, 8192, 512, 512, 512);
    init_ln_k<<<8192, 128>>>(b_init, g_init, beta_init);

    for (int i = 0; i < 63; i++) {
        int Scur = 64 - i;
        int P = Scur - 1;
        select_k<<<NB, 256>>>(W_d1, b_d1, W_d2, b_d2, mask, i, P, (i == 62) ? 1 : 0);
        // fc1: xcat(128x1024) @ W_c1(1024x2048), split-K=16 (chunks of 64)
        sgemm_k<<<dim3(16, 1, SPLITK), 256>>>(p_xcat, W_c1, p_part, 128, 2048, 1024, 64);
        fc1red_k<<<(NB * CHD) / 256, 256>>>(b_c1);
        // fc2: h(128x2048) @ W_c2(2048x2048), split-K=16 (chunks of 128)
        sgemm_k<<<dim3(16, 1, SPLITK), 256>>>(p_h, W_c2, p_part, 128, 2048, 2048, 128);
        gateln_k<<<NB, 256>>>(b_c2, g_c, beta_c, 0);
    }
    gather_k<<<NB, 256>>>((float*)d_out);
}